// round 13
// baseline (speedup 1.0000x reference)
#include <cuda_runtime.h>
#include <cuda_fp16.h>
#include <cstdint>

#define V    50000
#define NNZ  1600000
#define Bb   4
#define FIN  128
#define FOUT 128
#define KK   5
#define F    (FIN * Bb)   // 512
#define M_TOT (Bb * V)    // 200000

// ---------------- scratch (static device arrays; no allocation) ----------------
__device__ __align__(256) __half g_xh[KK][V * F];   // fp16 Chebyshev terms [v][b][fin]
__device__ int   g_colsS[NNZ];
__device__ float g_valsS[NNZ];
__device__ int   g_rowstart[V + 1];
__device__ int   g_cnt[V];
__device__ __align__(256) __half g_Wh[FOUT * KK * FIN]; // [n][k] K-major, k=kb*128+fin

// ---------------- helpers ----------------
__device__ __forceinline__ uint32_t smem_u32(const void* p) {
    uint32_t a;
    asm("{ .reg .u64 t; cvta.to.shared.u64 t, %1; cvt.u32.u64 %0, t; }" : "=r"(a) : "l"(p));
    return a;
}
__device__ __forceinline__ void cp16(uint32_t dst, const void* src) {
    asm volatile("cp.async.cg.shared.global [%0], [%1], 16;" :: "r"(dst), "l"(src));
}
__device__ __forceinline__ void ldmatrix_x4(uint32_t& r0, uint32_t& r1, uint32_t& r2,
                                            uint32_t& r3, uint32_t addr) {
    asm volatile("ldmatrix.sync.aligned.m8n8.x4.shared.b16 {%0,%1,%2,%3}, [%4];"
                 : "=r"(r0), "=r"(r1), "=r"(r2), "=r"(r3) : "r"(addr));
}
__device__ __forceinline__ void mma_16816(float& c0, float& c1, float& c2, float& c3,
                                          uint32_t a0, uint32_t a1, uint32_t a2, uint32_t a3,
                                          uint32_t b0, uint32_t b1) {
    asm volatile(
        "mma.sync.aligned.m16n8k16.row.col.f32.f16.f16.f32 "
        "{%0,%1,%2,%3}, {%4,%5,%6,%7}, {%8,%9}, {%0,%1,%2,%3};"
        : "+f"(c0), "+f"(c1), "+f"(c2), "+f"(c3)
        : "r"(a0), "r"(a1), "r"(a2), "r"(a3), "r"(b0), "r"(b1));
}

// ---------------- CSR build ----------------
__global__ void zero_cnt_kernel() {
    int i = blockIdx.x * blockDim.x + threadIdx.x;
    if (i < V) g_cnt[i] = 0;
}
__global__ void count_kernel(const int* __restrict__ rows) {
    int i = blockIdx.x * blockDim.x + threadIdx.x;
    if (i < NNZ) atomicAdd(&g_cnt[rows[i]], 1);
}
// single-block exclusive scan (warp-shuffle based), re-zeros g_cnt
__global__ __launch_bounds__(1024) void scan_kernel() {
    __shared__ int warp_sums[32];
    int tid = threadIdx.x;
    int lane = tid & 31, w = tid >> 5;
    int carry = 0;
    for (int base = 0; base < V; base += 1024) {
        int i = base + tid;
        int x = 0;
        if (i < V) { x = g_cnt[i]; g_cnt[i] = 0; }
        int v = x;
#pragma unroll
        for (int off = 1; off < 32; off <<= 1) {
            int t = __shfl_up_sync(0xFFFFFFFFu, v, off);
            if (lane >= off) v += t;
        }
        if (lane == 31) warp_sums[w] = v;
        __syncthreads();
        if (w == 0) {
            int s = warp_sums[lane];
#pragma unroll
            for (int off = 1; off < 32; off <<= 1) {
                int t = __shfl_up_sync(0xFFFFFFFFu, s, off);
                if (lane >= off) s += t;
            }
            warp_sums[lane] = s;
        }
        __syncthreads();
        int wbase = (w > 0) ? warp_sums[w - 1] : 0;
        if (i < V) g_rowstart[i] = carry + wbase + v - x;   // exclusive
        carry += warp_sums[31];
        __syncthreads();
    }
    if (tid == 0) g_rowstart[V] = carry;
}
__global__ void scatter_kernel(const int* __restrict__ rows,
                               const int* __restrict__ cols,
                               const float* __restrict__ vals) {
    int i = blockIdx.x * blockDim.x + threadIdx.x;
    if (i < NNZ) {
        int r = rows[i];
        int p = g_rowstart[r] + atomicAdd(&g_cnt[r], 1);
        g_colsS[p] = cols[i];
        g_valsS[p] = vals[i];
    }
}

// ---------------- weight repack: g_Wh[n][kb*128+fin] = Wraw[(fin*5+kb)*128+n] (fp16) ---
__global__ void repack_w_kernel(const float* __restrict__ w) {
    int kk = blockIdx.x;          // kb*128 + fin
    int n  = threadIdx.x;
    int kb = kk >> 7;
    int fin = kk & 127;
    g_Wh[n * (KK * FIN) + kk] = __float2half(w[(fin * KK + kb) * FOUT + n]);
}

// ---------------- transpose: inputs[b][v][fin] -> x0[v][b][fin] (fp16 only) ------------
__global__ void transpose_kernel(const float* __restrict__ inp) {
    int v = blockIdx.x, b = blockIdx.y, t = threadIdx.x;
    float val = inp[((long)b * V + v) * FIN + t];
    g_xh[0][(v * Bb + b) * FIN + t] = __float2half(val);
}

// ---------------- SpMM (fp16 gather/store, fp32 accum): x[kout] = a*L@x[kin] - x[ksub]
// unroll x4 -> 4 independent L2 gathers in flight per thread (MLP_eff ~4)
__global__ __launch_bounds__(256) void spmm_kernel(int kin, int ksub, int kout, float alpha) {
    int v = blockIdx.x;
    int t = threadIdx.x;   // handles features 2t, 2t+1
    const __half2* __restrict__ xin = (const __half2*)g_xh[kin];
    const int*   __restrict__ colp = g_colsS;
    const float* __restrict__ valp = g_valsS;
    int s = g_rowstart[v];
    int e = g_rowstart[v + 1];
    float ax0 = 0.f, ay0 = 0.f, ax1 = 0.f, ay1 = 0.f;
    float ax2 = 0.f, ay2 = 0.f, ax3 = 0.f, ay3 = 0.f;
    int i = s;
    for (; i + 4 <= e; i += 4) {
        int   c0 = colp[i],     c1 = colp[i + 1];
        int   c2 = colp[i + 2], c3 = colp[i + 3];
        float w0 = valp[i],     w1 = valp[i + 1];
        float w2 = valp[i + 2], w3 = valp[i + 3];
        __half2 h0 = xin[c0 * (F / 2) + t];
        __half2 h1 = xin[c1 * (F / 2) + t];
        __half2 h2 = xin[c2 * (F / 2) + t];
        __half2 h3 = xin[c3 * (F / 2) + t];
        float2 f0 = __half22float2(h0);
        float2 f1 = __half22float2(h1);
        float2 f2 = __half22float2(h2);
        float2 f3 = __half22float2(h3);
        ax0 += w0 * f0.x; ay0 += w0 * f0.y;
        ax1 += w1 * f1.x; ay1 += w1 * f1.y;
        ax2 += w2 * f2.x; ay2 += w2 * f2.y;
        ax3 += w3 * f3.x; ay3 += w3 * f3.y;
    }
    for (; i < e; ++i) {
        int c = colp[i]; float w = valp[i];
        float2 f = __half22float2(xin[c * (F / 2) + t]);
        ax0 += w * f.x; ay0 += w * f.y;
    }
    float rx = alpha * ((ax0 + ax1) + (ax2 + ax3));
    float ry = alpha * ((ay0 + ay1) + (ay2 + ay3));
    int o = v * (F / 2) + t;
    if (ksub >= 0) {
        float2 p = __half22float2(((const __half2*)g_xh[ksub])[o]);
        rx -= p.x; ry -= p.y;
    }
    ((__half2*)g_xh[kout])[o] = __floats2half2_rn(rx, ry);
}

// ---------------- HMMA GEMM: out[m][n] = sum_k A[m][k] * Wh[n][k] + bias ----------------
// A[m][kb*128+fin] = g_xh[kb][(v*4+b)*128+fin], m = b*V+v. K=640 in 10 chunks of 64 halves.
// Block: 128x128 tile, 256 threads (8 warps, 64x32 warp tiles). Double-buffered cp.async.
#define BK      64
#define ASTRH   72                       // padded row stride in halves (144B)
#define TILE_B  (128 * ASTRH * 2)        // 18432 bytes per operand tile
#define BUF_B   (2 * TILE_B)             // A + W per buffer
#define SMEM_DYN (2 * BUF_B)             // 73728 bytes

__global__ __launch_bounds__(256) void gemm_hmma_kernel(const float* __restrict__ bias,
                                                        float* __restrict__ out) {
    extern __shared__ char smem[];
    uint32_t sb = smem_u32(smem);
    int tid = threadIdx.x;
    int lane = tid & 31, wid = tid >> 5;
    int wm = wid & 1, wn = wid >> 1;     // warp grid 2 (M) x 4 (N)
    int m0 = blockIdx.x * 128;

    // ---- load mapping: thread covers 64B (4 x 16B) of one 128B row; 2 threads/row ----
    int lrow = tid >> 1;                  // 0..127
    int lseg = (tid & 1) * 4;             // starting 16B segment
    int am = m0 + lrow;
    if (am >= M_TOT) am = M_TOT - 1;      // clamp (results guarded at store)
    int b = am / V;
    int v = am - b * V;
    int arow = (v * Bb + b) * FIN;        // half offset into g_xh[kb]

    uint32_t a_dst_base = sb + lrow * (ASTRH * 2) + lseg * 16;
    uint32_t w_dst_base = a_dst_base + TILE_B;
    const __half* wsrc_row = &g_Wh[lrow * (KK * FIN)];

    auto issue = [&](int c) {
        int kb = c >> 1;
        const __half* as = &g_xh[kb][arow + (c & 1) * BK + lseg * 8];
        const __half* ws = wsrc_row + c * BK + lseg * 8;
        uint32_t base = (c & 1) * BUF_B;
#pragma unroll
        for (int i = 0; i < 4; ++i) {
            cp16(a_dst_base + base + i * 16, as + i * 8);
            cp16(w_dst_base + base + i * 16, ws + i * 8);
        }
        asm volatile("cp.async.commit_group;" ::: "memory");
    };

    float acc[4][4][4];                   // [mi][ni][reg]
#pragma unroll
    for (int mi = 0; mi < 4; ++mi)
#pragma unroll
        for (int ni = 0; ni < 4; ++ni)
#pragma unroll
            for (int r = 0; r < 4; ++r) acc[mi][ni][r] = 0.f;

    issue(0);
    issue(1);

    // per-lane ldmatrix address pieces (A): row = Rbase + (lane&15), col = ks*16 + (lane>>4)*8
    int a_lrow = lane & 15;
    int a_lcol = (lane >> 4) << 3;
    // B direct-load pieces: n = base + lane>>2, k = ks*16 + (lane&3)*2
    int b_ln = lane >> 2;
    int b_lk = (lane & 3) * 2;

    for (int c = 0; c < 10; ++c) {
        if (c == 9) asm volatile("cp.async.wait_group 0;" ::: "memory");
        else        asm volatile("cp.async.wait_group 1;" ::: "memory");
        __syncthreads();

        uint32_t abase = sb + (c & 1) * BUF_B;
#pragma unroll
        for (int ks = 0; ks < 4; ++ks) {
            uint32_t a[4][4];
#pragma unroll
            for (int mi = 0; mi < 4; ++mi) {
                int row = wm * 64 + mi * 16 + a_lrow;
                int col = ks * 16 + a_lcol;
                ldmatrix_x4(a[mi][0], a[mi][1], a[mi][2], a[mi][3],
                            abase + row * (ASTRH * 2) + col * 2);
            }
            uint32_t bfr[4][2];
#pragma unroll
            for (int ni = 0; ni < 4; ++ni) {
                int n = wn * 32 + ni * 8 + b_ln;
                const __half* bp = (const __half*)(smem + (c & 1) * BUF_B + TILE_B) +
                                   n * ASTRH + ks * 16 + b_lk;
                bfr[ni][0] = *(const uint32_t*)bp;
                bfr[ni][1] = *(const uint32_t*)(bp + 8);
            }
#pragma unroll
            for (int mi = 0; mi < 4; ++mi)
#pragma unroll
                for (int ni = 0; ni < 4; ++ni)
                    mma_16816(acc[mi][ni][0], acc[mi][ni][1], acc[mi][ni][2], acc[mi][ni][3],
                              a[mi][0], a[mi][1], a[mi][2], a[mi][3],
                              bfr[ni][0], bfr[ni][1]);
        }
        __syncthreads();
        if (c + 2 < 10) issue(c + 2);
    }

    // ---- epilogue: d0,d1 -> row lane>>2, cols +0,+1 ; d2,d3 -> row+8 ----
#pragma unroll
    for (int mi = 0; mi < 4; ++mi) {
        int r0 = m0 + wm * 64 + mi * 16 + (lane >> 2);
        int r1 = r0 + 8;
#pragma unroll
        for (int ni = 0; ni < 4; ++ni) {
            int col = wn * 32 + ni * 8 + (lane & 3) * 2;
            float bx = bias[col], by = bias[col + 1];
            if (r0 < M_TOT)
                *(float2*)&out[(long)r0 * FOUT + col] =
                    make_float2(acc[mi][ni][0] + bx, acc[mi][ni][1] + by);
            if (r1 < M_TOT)
                *(float2*)&out[(long)r1 * FOUT + col] =
                    make_float2(acc[mi][ni][2] + bx, acc[mi][ni][3] + by);
        }
    }
}

// ---------------- launch ----------------
extern "C" void kernel_launch(void* const* d_in, const int* in_sizes, int n_in,
                              void* d_out, int out_size) {
    const int*   rows = (const int*)d_in[0];
    const int*   cols = (const int*)d_in[1];
    const float* vals = (const float*)d_in[2];
    const float* inp  = (const float*)d_in[3];
    const float* w    = (const float*)d_in[4];
    const float* bias = (const float*)d_in[5];
    float* out = (float*)d_out;

    cudaFuncSetAttribute(gemm_hmma_kernel, cudaFuncAttributeMaxDynamicSharedMemorySize, SMEM_DYN);

    zero_cnt_kernel<<<(V + 255) / 256, 256>>>();
    count_kernel<<<(NNZ + 255) / 256, 256>>>(rows);
    scan_kernel<<<1, 1024>>>();
    scatter_kernel<<<(NNZ + 255) / 256, 256>>>(rows, cols, vals);
    repack_w_kernel<<<KK * FIN, FOUT>>>(w);
    transpose_kernel<<<dim3(V, Bb), FIN>>>(inp);

    spmm_kernel<<<V, 256>>>(0, -1, 1, 1.0f);
    spmm_kernel<<<V, 256>>>(1,  0, 2, 2.0f);
    spmm_kernel<<<V, 256>>>(2,  1, 3, 2.0f);
    spmm_kernel<<<V, 256>>>(3,  2, 4, 2.0f);

    gemm_hmma_kernel<<<(M_TOT + 127) / 128, 256, SMEM_DYN>>>(bias, out);
}

// round 14
// speedup vs baseline: 1.3054x; 1.3054x over previous
#include <cuda_runtime.h>
#include <cuda_fp16.h>
#include <cstdint>

#define V    50000
#define NNZ  1600000
#define Bb   4
#define FIN  128
#define FOUT 128
#define KK   5
#define F    (FIN * Bb)   // 512
#define M_TOT (Bb * V)    // 200000

// ---------------- scratch (static device arrays; no allocation) ----------------
__device__ __align__(256) __half g_xh[KK][V * F];   // fp16 Chebyshev terms [v][b][fin]
__device__ __align__(16) int2 g_edge[NNZ];          // packed {col, val_bits}
__device__ int   g_rowstart[V + 1];
__device__ int   g_cnt[V];
__device__ __align__(256) __half g_Wh[FOUT * KK * FIN]; // [n][k] K-major, k=kb*128+fin

// ---------------- helpers ----------------
__device__ __forceinline__ uint32_t smem_u32(const void* p) {
    uint32_t a;
    asm("{ .reg .u64 t; cvta.to.shared.u64 t, %1; cvt.u32.u64 %0, t; }" : "=r"(a) : "l"(p));
    return a;
}
__device__ __forceinline__ void cp16(uint32_t dst, const void* src) {
    asm volatile("cp.async.cg.shared.global [%0], [%1], 16;" :: "r"(dst), "l"(src));
}
__device__ __forceinline__ void ldmatrix_x4(uint32_t& r0, uint32_t& r1, uint32_t& r2,
                                            uint32_t& r3, uint32_t addr) {
    asm volatile("ldmatrix.sync.aligned.m8n8.x4.shared.b16 {%0,%1,%2,%3}, [%4];"
                 : "=r"(r0), "=r"(r1), "=r"(r2), "=r"(r3) : "r"(addr));
}
__device__ __forceinline__ void mma_16816(float& c0, float& c1, float& c2, float& c3,
                                          uint32_t a0, uint32_t a1, uint32_t a2, uint32_t a3,
                                          uint32_t b0, uint32_t b1) {
    asm volatile(
        "mma.sync.aligned.m16n8k16.row.col.f32.f16.f16.f32 "
        "{%0,%1,%2,%3}, {%4,%5,%6,%7}, {%8,%9}, {%0,%1,%2,%3};"
        : "+f"(c0), "+f"(c1), "+f"(c2), "+f"(c3)
        : "r"(a0), "r"(a1), "r"(a2), "r"(a3), "r"(b0), "r"(b1));
}

// ---------------- CSR build ----------------
__global__ void zero_cnt_kernel() {
    int i = blockIdx.x * blockDim.x + threadIdx.x;
    if (i < V) g_cnt[i] = 0;
}
__global__ void count_kernel(const int* __restrict__ rows) {
    int i = blockIdx.x * blockDim.x + threadIdx.x;
    if (i < NNZ) atomicAdd(&g_cnt[rows[i]], 1);
}
// single-block exclusive scan (warp-shuffle based), re-zeros g_cnt
__global__ __launch_bounds__(1024) void scan_kernel() {
    __shared__ int warp_sums[32];
    int tid = threadIdx.x;
    int lane = tid & 31, w = tid >> 5;
    int carry = 0;
    for (int base = 0; base < V; base += 1024) {
        int i = base + tid;
        int x = 0;
        if (i < V) { x = g_cnt[i]; g_cnt[i] = 0; }
        int v = x;
#pragma unroll
        for (int off = 1; off < 32; off <<= 1) {
            int t = __shfl_up_sync(0xFFFFFFFFu, v, off);
            if (lane >= off) v += t;
        }
        if (lane == 31) warp_sums[w] = v;
        __syncthreads();
        if (w == 0) {
            int s = warp_sums[lane];
#pragma unroll
            for (int off = 1; off < 32; off <<= 1) {
                int t = __shfl_up_sync(0xFFFFFFFFu, s, off);
                if (lane >= off) s += t;
            }
            warp_sums[lane] = s;
        }
        __syncthreads();
        int wbase = (w > 0) ? warp_sums[w - 1] : 0;
        if (i < V) g_rowstart[i] = carry + wbase + v - x;   // exclusive
        carry += warp_sums[31];
        __syncthreads();
    }
    if (tid == 0) g_rowstart[V] = carry;
}
__global__ void scatter_kernel(const int* __restrict__ rows,
                               const int* __restrict__ cols,
                               const float* __restrict__ vals) {
    int i = blockIdx.x * blockDim.x + threadIdx.x;
    if (i < NNZ) {
        int r = rows[i];
        int p = g_rowstart[r] + atomicAdd(&g_cnt[r], 1);
        g_edge[p] = make_int2(cols[i], __float_as_int(vals[i]));
    }
}

// ---------------- weight repack: g_Wh[n][kb*128+fin] = Wraw[(fin*5+kb)*128+n] (fp16) ---
__global__ void repack_w_kernel(const float* __restrict__ w) {
    int kk = blockIdx.x;          // kb*128 + fin
    int n  = threadIdx.x;
    int kb = kk >> 7;
    int fin = kk & 127;
    g_Wh[n * (KK * FIN) + kk] = __float2half(w[(fin * KK + kb) * FOUT + n]);
}

// ---------------- transpose: inputs[b][v][fin] -> x0[v][b][fin] (fp16 only) ------------
__global__ void transpose_kernel(const float* __restrict__ inp) {
    int v = blockIdx.x, b = blockIdx.y, t = threadIdx.x;
    float val = inp[((long)b * V + v) * FIN + t];
    g_xh[0][(v * Bb + b) * FIN + t] = __float2half(val);
}

// ---------------- SpMM: x[kout] = alpha * L @ x[kin] - x[ksub] --------------------------
// 256 threads = 4 edge-groups x 64 threads. Each thread gathers 8 halves via LDG.128.
// Per edge: 2 warp gather-LDGs + 2 idx LDGs (vs 24 in the scalar version).
__global__ __launch_bounds__(256) void spmm_kernel(int kin, int ksub, int kout, float alpha) {
    __shared__ float red[4][64][8];
    int v = blockIdx.x;
    int tid = threadIdx.x;
    int eg = tid >> 6;          // 0..3 edge group
    int ft = tid & 63;          // feature slot: halves [ft*8, ft*8+8)
    const uint4* __restrict__ xin = (const uint4*)g_xh[kin];   // row pitch = 64 uint4
    const int2* __restrict__ ep = g_edge;
    int s = g_rowstart[v];
    int e = g_rowstart[v + 1];

    float acc[8];
#pragma unroll
    for (int j = 0; j < 8; ++j) acc[j] = 0.f;

    for (int i = s + eg; i < e; i += 4) {
        int2 ev = __ldg(&ep[i]);
        float w = __int_as_float(ev.y);
        uint4 h = xin[ev.x * 64 + ft];
        float2 f0 = __half22float2(*(__half2*)&h.x);
        float2 f1 = __half22float2(*(__half2*)&h.y);
        float2 f2 = __half22float2(*(__half2*)&h.z);
        float2 f3 = __half22float2(*(__half2*)&h.w);
        acc[0] += w * f0.x; acc[1] += w * f0.y;
        acc[2] += w * f1.x; acc[3] += w * f1.y;
        acc[4] += w * f2.x; acc[5] += w * f2.y;
        acc[6] += w * f3.x; acc[7] += w * f3.y;
    }

    // stage partials (conflict-free in 128-bit phases)
#pragma unroll
    for (int j = 0; j < 4; ++j)
        *(float2*)&red[eg][ft][j * 2] = make_float2(acc[j * 2], acc[j * 2 + 1]);
    __syncthreads();

    if (eg == 0) {
#pragma unroll
        for (int j = 0; j < 8; ++j)
            acc[j] = alpha * (acc[j] + red[1][ft][j] + red[2][ft][j] + red[3][ft][j]);
        if (ksub >= 0) {
            uint4 p = ((const uint4*)g_xh[ksub])[v * 64 + ft];
            float2 p0 = __half22float2(*(__half2*)&p.x);
            float2 p1 = __half22float2(*(__half2*)&p.y);
            float2 p2 = __half22float2(*(__half2*)&p.z);
            float2 p3 = __half22float2(*(__half2*)&p.w);
            acc[0] -= p0.x; acc[1] -= p0.y;
            acc[2] -= p1.x; acc[3] -= p1.y;
            acc[4] -= p2.x; acc[5] -= p2.y;
            acc[6] -= p3.x; acc[7] -= p3.y;
        }
        uint4 o;
        *(__half2*)&o.x = __floats2half2_rn(acc[0], acc[1]);
        *(__half2*)&o.y = __floats2half2_rn(acc[2], acc[3]);
        *(__half2*)&o.z = __floats2half2_rn(acc[4], acc[5]);
        *(__half2*)&o.w = __floats2half2_rn(acc[6], acc[7]);
        ((uint4*)g_xh[kout])[v * 64 + ft] = o;
    }
}

// ---------------- HMMA GEMM: out[m][n] = sum_k A[m][k] * Wh[n][k] + bias ----------------
#define BK      64
#define ASTRH   72                       // padded row stride in halves (144B)
#define TILE_B  (128 * ASTRH * 2)        // 18432 bytes per operand tile
#define BUF_B   (2 * TILE_B)             // A + W per buffer
#define SMEM_DYN (2 * BUF_B)             // 73728 bytes

__global__ __launch_bounds__(256) void gemm_hmma_kernel(const float* __restrict__ bias,
                                                        float* __restrict__ out) {
    extern __shared__ char smem[];
    uint32_t sb = smem_u32(smem);
    int tid = threadIdx.x;
    int lane = tid & 31, wid = tid >> 5;
    int wm = wid & 1, wn = wid >> 1;     // warp grid 2 (M) x 4 (N)
    int m0 = blockIdx.x * 128;

    int lrow = tid >> 1;                  // 0..127
    int lseg = (tid & 1) * 4;             // starting 16B segment
    int am = m0 + lrow;
    if (am >= M_TOT) am = M_TOT - 1;      // clamp (results guarded at store)
    int b = am / V;
    int v = am - b * V;
    int arow = (v * Bb + b) * FIN;        // half offset into g_xh[kb]

    uint32_t a_dst_base = sb + lrow * (ASTRH * 2) + lseg * 16;
    uint32_t w_dst_base = a_dst_base + TILE_B;
    const __half* wsrc_row = &g_Wh[lrow * (KK * FIN)];

    auto issue = [&](int c) {
        int kb = c >> 1;
        const __half* as = &g_xh[kb][arow + (c & 1) * BK + lseg * 8];
        const __half* ws = wsrc_row + c * BK + lseg * 8;
        uint32_t base = (c & 1) * BUF_B;
#pragma unroll
        for (int i = 0; i < 4; ++i) {
            cp16(a_dst_base + base + i * 16, as + i * 8);
            cp16(w_dst_base + base + i * 16, ws + i * 8);
        }
        asm volatile("cp.async.commit_group;" ::: "memory");
    };

    float acc[4][4][4];                   // [mi][ni][reg]
#pragma unroll
    for (int mi = 0; mi < 4; ++mi)
#pragma unroll
        for (int ni = 0; ni < 4; ++ni)
#pragma unroll
            for (int r = 0; r < 4; ++r) acc[mi][ni][r] = 0.f;

    issue(0);
    issue(1);

    int a_lrow = lane & 15;
    int a_lcol = (lane >> 4) << 3;
    int b_ln = lane >> 2;
    int b_lk = (lane & 3) * 2;

    for (int c = 0; c < 10; ++c) {
        if (c == 9) asm volatile("cp.async.wait_group 0;" ::: "memory");
        else        asm volatile("cp.async.wait_group 1;" ::: "memory");
        __syncthreads();

        uint32_t abase = sb + (c & 1) * BUF_B;
#pragma unroll
        for (int ks = 0; ks < 4; ++ks) {
            uint32_t a[4][4];
#pragma unroll
            for (int mi = 0; mi < 4; ++mi) {
                int row = wm * 64 + mi * 16 + a_lrow;
                int col = ks * 16 + a_lcol;
                ldmatrix_x4(a[mi][0], a[mi][1], a[mi][2], a[mi][3],
                            abase + row * (ASTRH * 2) + col * 2);
            }
            uint32_t bfr[4][2];
#pragma unroll
            for (int ni = 0; ni < 4; ++ni) {
                int n = wn * 32 + ni * 8 + b_ln;
                const __half* bp = (const __half*)(smem + (c & 1) * BUF_B + TILE_B) +
                                   n * ASTRH + ks * 16 + b_lk;
                bfr[ni][0] = *(const uint32_t*)bp;
                bfr[ni][1] = *(const uint32_t*)(bp + 8);
            }
#pragma unroll
            for (int mi = 0; mi < 4; ++mi)
#pragma unroll
                for (int ni = 0; ni < 4; ++ni)
                    mma_16816(acc[mi][ni][0], acc[mi][ni][1], acc[mi][ni][2], acc[mi][ni][3],
                              a[mi][0], a[mi][1], a[mi][2], a[mi][3],
                              bfr[ni][0], bfr[ni][1]);
        }
        __syncthreads();
        if (c + 2 < 10) issue(c + 2);
    }

#pragma unroll
    for (int mi = 0; mi < 4; ++mi) {
        int r0 = m0 + wm * 64 + mi * 16 + (lane >> 2);
        int r1 = r0 + 8;
#pragma unroll
        for (int ni = 0; ni < 4; ++ni) {
            int col = wn * 32 + ni * 8 + (lane & 3) * 2;
            float bx = bias[col], by = bias[col + 1];
            if (r0 < M_TOT)
                *(float2*)&out[(long)r0 * FOUT + col] =
                    make_float2(acc[mi][ni][0] + bx, acc[mi][ni][1] + by);
            if (r1 < M_TOT)
                *(float2*)&out[(long)r1 * FOUT + col] =
                    make_float2(acc[mi][ni][2] + bx, acc[mi][ni][3] + by);
        }
    }
}

// ---------------- launch ----------------
extern "C" void kernel_launch(void* const* d_in, const int* in_sizes, int n_in,
                              void* d_out, int out_size) {
    const int*   rows = (const int*)d_in[0];
    const int*   cols = (const int*)d_in[1];
    const float* vals = (const float*)d_in[2];
    const float* inp  = (const float*)d_in[3];
    const float* w    = (const float*)d_in[4];
    const float* bias = (const float*)d_in[5];
    float* out = (float*)d_out;

    cudaFuncSetAttribute(gemm_hmma_kernel, cudaFuncAttributeMaxDynamicSharedMemorySize, SMEM_DYN);

    zero_cnt_kernel<<<(V + 255) / 256, 256>>>();
    count_kernel<<<(NNZ + 255) / 256, 256>>>(rows);
    scan_kernel<<<1, 1024>>>();
    scatter_kernel<<<(NNZ + 255) / 256, 256>>>(rows, cols, vals);
    repack_w_kernel<<<KK * FIN, FOUT>>>(w);
    transpose_kernel<<<dim3(V, Bb), FIN>>>(inp);

    spmm_kernel<<<V, 256>>>(0, -1, 1, 1.0f);
    spmm_kernel<<<V, 256>>>(1,  0, 2, 2.0f);
    spmm_kernel<<<V, 256>>>(2,  1, 3, 2.0f);
    spmm_kernel<<<V, 256>>>(3,  2, 4, 2.0f);

    gemm_hmma_kernel<<<(M_TOT + 127) / 128, 256, SMEM_DYN>>>(bias, out);
}